// round 14
// baseline (speedup 1.0000x reference)
#include <cuda_runtime.h>
#include <cuda_fp16.h>
#include <cstdint>

#define N_NODES   50000
#define N_EDGES   800000
#define IN_FEATS  256
#define OUT_FEATS 64
#define CAP       64          // bucket capacity; P(Poisson(16) > 64) ~ 2e-18/node
#define DUMMY     50000       // dummy src id -> all-zero row of g_hw_h

// Scratch (__device__ globals: no allocation allowed)
__device__ __half    g_hw_h[(N_NODES + 1) * OUT_FEATS]; // +1 zero dummy row
__device__ uint32_t  g_w_tf32[IN_FEATS * OUT_FEATS];    // W pre-converted to tf32
__device__ int       g_cnt[N_NODES];                    // per-dst degree counters
__device__ uint16_t  g_esrc16[N_NODES * CAP];           // bucketed src ids (6.4MB)

// ---------------------------------------------------------------------------
// Kernel 0: tiny init -- W->tf32, counter zero, dummy row. Serial, ~1us.
// ---------------------------------------------------------------------------
__global__ __launch_bounds__(256)
void init_kernel(const float* __restrict__ W) {
    int gid = blockIdx.x * blockDim.x + threadIdx.x;   // 50176 threads
    if (gid < N_NODES) g_cnt[gid] = 0;
    if (gid < OUT_FEATS / 8)
        *reinterpret_cast<uint4*>(g_hw_h + (size_t)DUMMY * OUT_FEATS + gid * 8) =
            make_uint4(0u, 0u, 0u, 0u);
    if (gid < IN_FEATS * OUT_FEATS / 4) {
        float4 v = *reinterpret_cast<const float4*>(W + gid * 4);
        uint4 u;
        asm("cvt.rna.tf32.f32 %0, %1;" : "=r"(u.x) : "f"(v.x));
        asm("cvt.rna.tf32.f32 %0, %1;" : "=r"(u.y) : "f"(v.y));
        asm("cvt.rna.tf32.f32 %0, %1;" : "=r"(u.z) : "f"(v.z));
        asm("cvt.rna.tf32.f32 %0, %1;" : "=r"(u.w) : "f"(v.w));
        *reinterpret_cast<uint4*>(g_w_tf32 + gid * 4) = u;
    }
}

// ---------------------------------------------------------------------------
// Kernel 0b: bucket pre-fill (runs on the place branch, overlapping GEMM).
// Purpose: pull g_esrc16 into L2 so place's scattered 2B stores are L2 hits.
// ---------------------------------------------------------------------------
__global__ __launch_bounds__(256)
void prefill_kernel() {
    int gid = blockIdx.x * blockDim.x + threadIdx.x;   // 400000 threads
    if (gid < N_NODES * CAP / 8) {
        uint4 f = make_uint4(0xC350C350u, 0xC350C350u, 0xC350C350u, 0xC350C350u);
        *reinterpret_cast<uint4*>(g_esrc16 + gid * 8) = f;
    }
}

// ---------------------------------------------------------------------------
// Kernel 1: hw = (h @ W) * norm  -- tf32 mma.sync, 3-stage cp.async pipeline.
// Tile 128x64, BK=32 (8 chunks), 256 threads. smem ~83KB -> 2 CTAs/SM.
// ---------------------------------------------------------------------------
#define PAD_A 36
#define PAD_B 72
#define STAGES 3

__device__ __forceinline__ uint32_t f2tf32(float f) {
    uint32_t u;
    asm("cvt.rna.tf32.f32 %0, %1;" : "=r"(u) : "f"(f));
    return u;
}

__device__ __forceinline__ void cp_async16(void* smem_dst, const void* gmem_src) {
    uint32_t s;
    asm("{ .reg .u64 t; cvta.to.shared.u64 t, %1; cvt.u32.u64 %0, t; }"
        : "=r"(s) : "l"(smem_dst));
    asm volatile("cp.async.cg.shared.global [%0], [%1], 16;" :: "r"(s), "l"(gmem_src));
}

__global__ __launch_bounds__(256, 2)
void gemm_tf32_kernel(const float* __restrict__ h,
                      const float* __restrict__ norm) {
    __shared__ uint32_t shA[STAGES][128 * PAD_A];
    __shared__ uint32_t shB[STAGES][32 * PAD_B];

    const int tid  = threadIdx.x;
    const int warp = tid >> 5;
    const int lane = tid & 31;
    const int g    = lane >> 2;
    const int tg   = lane & 3;
    const int rowBase = blockIdx.x * 128;

    float acc[8][4];
    #pragma unroll
    for (int t = 0; t < 8; t++)
        #pragma unroll
        for (int i = 0; i < 4; i++) acc[t][i] = 0.f;

    auto stage = [&](int kk, int b) {
        #pragma unroll
        for (int j = 0; j < 4; j++) {
            int idx = tid + j * 256;
            int r   = idx >> 3;
            int k4  = idx & 7;
            int row = rowBase + r;
            if (row >= N_NODES) row = N_NODES - 1;   // clamp: junk computed, never stored
            cp_async16(&shA[b][r * PAD_A + k4 * 4],
                       h + (size_t)row * IN_FEATS + kk + k4 * 4);
        }
        #pragma unroll
        for (int j = 0; j < 2; j++) {
            int idx = tid + j * 256;
            int r   = idx >> 4;
            int k4  = idx & 15;
            cp_async16(&shB[b][r * PAD_B + k4 * 4],
                       g_w_tf32 + (size_t)(kk + r) * OUT_FEATS + k4 * 4);
        }
        asm volatile("cp.async.commit_group;" ::: "memory");
    };

    stage(0, 0);
    stage(32, 1);

    #pragma unroll
    for (int c = 0; c < 8; c++) {
        if (c < 7) asm volatile("cp.async.wait_group 1;" ::: "memory");
        else       asm volatile("cp.async.wait_group 0;" ::: "memory");
        __syncthreads();
        if (c + 2 < 8) stage((c + 2) * 32, (c + 2) % STAGES);

        const uint32_t* A = shA[c % STAGES];
        const uint32_t* B = shB[c % STAGES];
        const int ar = warp * 16;
        #pragma unroll
        for (int k8 = 0; k8 < 32; k8 += 8) {
            uint32_t a0 = f2tf32(__uint_as_float(A[(ar + g    ) * PAD_A + k8 + tg    ]));
            uint32_t a1 = f2tf32(__uint_as_float(A[(ar + g + 8) * PAD_A + k8 + tg    ]));
            uint32_t a2 = f2tf32(__uint_as_float(A[(ar + g    ) * PAD_A + k8 + tg + 4]));
            uint32_t a3 = f2tf32(__uint_as_float(A[(ar + g + 8) * PAD_A + k8 + tg + 4]));
            #pragma unroll
            for (int t = 0; t < 8; t++) {
                uint32_t b0 = B[(k8 + tg    ) * PAD_B + t * 8 + g];
                uint32_t b1 = B[(k8 + tg + 4) * PAD_B + t * 8 + g];
                asm volatile(
                    "mma.sync.aligned.m16n8k8.row.col.f32.tf32.tf32.f32 "
                    "{%0,%1,%2,%3}, {%4,%5,%6,%7}, {%8,%9}, {%0,%1,%2,%3};"
                    : "+f"(acc[t][0]), "+f"(acc[t][1]), "+f"(acc[t][2]), "+f"(acc[t][3])
                    : "r"(a0), "r"(a1), "r"(a2), "r"(a3), "r"(b0), "r"(b1));
            }
        }
        __syncthreads();
    }

    int r0 = rowBase + warp * 16 + g;
    int r1 = r0 + 8;
    if (r0 < N_NODES) {
        float nv = norm[r0];
        #pragma unroll
        for (int t = 0; t < 8; t++) {
            __half2 p = __floats2half2_rn(acc[t][0] * nv, acc[t][1] * nv);
            *reinterpret_cast<__half2*>(g_hw_h + (size_t)r0 * OUT_FEATS + t * 8 + tg * 2) = p;
        }
    }
    if (r1 < N_NODES) {
        float nv = norm[r1];
        #pragma unroll
        for (int t = 0; t < 8; t++) {
            __half2 p = __floats2half2_rn(acc[t][2] * nv, acc[t][3] * nv);
            *reinterpret_cast<__half2*>(g_hw_h + (size_t)r1 * OUT_FEATS + t * 8 + tg * 2) = p;
        }
    }
}

// ---------------------------------------------------------------------------
// Kernel 2: bucket placement, 1 edge per thread, uint16 src ids.
// ---------------------------------------------------------------------------
__global__ __launch_bounds__(256)
void place_kernel(const int* __restrict__ src, const int* __restrict__ dst) {
    int e = blockIdx.x * blockDim.x + threadIdx.x;
    if (e < N_EDGES) {
        int d = __ldg(dst + e);
        int s = __ldg(src + e);
        int p = atomicAdd(&g_cnt[d], 1);
        g_esrc16[d * CAP + (p & (CAP - 1))] = (uint16_t)s;  // masked: OOB-safe
    }
}

// ---------------------------------------------------------------------------
// Kernel 3: WARP-PER-NODE aggregation + fused epilogue.
// lane = (e, c): e = lane>>3 in 0..3 (edge slot), c = lane&7 (col group, 16B).
// Whole warp shares one node's loop bound -> zero divergence; pad-to-4 only;
// tail slots -> DUMMY (L1-hot zero row). shfl_xor(8,16) reduces over e.
// ---------------------------------------------------------------------------
__global__ __launch_bounds__(256)
void aggregate_kernel(const float* __restrict__ norm,
                      const float* __restrict__ bias,
                      float* __restrict__ out) {
    int v    = (blockIdx.x * blockDim.x + threadIdx.x) >> 5;   // one warp per node
    int lane = threadIdx.x & 31;
    if (v >= N_NODES) return;
    int c = lane & 7;        // col group (8 cols = 16B)
    int e = lane >> 3;       // edge slot 0..3

    const uint16_t* el = g_esrc16 + (size_t)v * CAP;
    int deg = g_cnt[v];
    if (deg > CAP) deg = CAP;
    int padded = (deg + 3) & ~3;

    float acc[8];
    #pragma unroll
    for (int i = 0; i < 8; i++) acc[i] = 0.f;

    for (int base = 0; base < padded; base += 4) {
        int idx = base + e;                       // < CAP always
        int id  = (idx < deg) ? (int)el[idx] : DUMMY;
        uint4 raw = *reinterpret_cast<const uint4*>(
            g_hw_h + (size_t)id * OUT_FEATS + c * 8);
        const __half2* hp = reinterpret_cast<const __half2*>(&raw);
        #pragma unroll
        for (int q = 0; q < 4; q++) {
            float2 f = __half22float2(hp[q]);
            acc[q * 2]     += f.x;
            acc[q * 2 + 1] += f.y;
        }
    }

    // reduce across the 4 edge slots (lanes c, c+8, c+16, c+24)
    #pragma unroll
    for (int i = 0; i < 8; i++) {
        acc[i] += __shfl_xor_sync(0xFFFFFFFFu, acc[i], 8);
        acc[i] += __shfl_xor_sync(0xFFFFFFFFu, acc[i], 16);
    }

    if (e == 0) {
        float nv = norm[v];
        const float4* bp = reinterpret_cast<const float4*>(bias + c * 8);
        float4 b0 = bp[0], b1 = bp[1];
        float4 o0, o1;
        o0.x = fmaxf(fmaf(acc[0], nv, b0.x), 0.f);
        o0.y = fmaxf(fmaf(acc[1], nv, b0.y), 0.f);
        o0.z = fmaxf(fmaf(acc[2], nv, b0.z), 0.f);
        o0.w = fmaxf(fmaf(acc[3], nv, b0.w), 0.f);
        o1.x = fmaxf(fmaf(acc[4], nv, b1.x), 0.f);
        o1.y = fmaxf(fmaf(acc[5], nv, b1.y), 0.f);
        o1.z = fmaxf(fmaf(acc[6], nv, b1.z), 0.f);
        o1.w = fmaxf(fmaf(acc[7], nv, b1.w), 0.f);
        float4* op = reinterpret_cast<float4*>(out + (size_t)v * OUT_FEATS + c * 8);
        op[0] = o0;
        op[1] = o1;
    }
}

// ---------------------------------------------------------------------------
// Launch: tiny init; fork {gemm} || {prefill -> place}; join; aggregate.
// ---------------------------------------------------------------------------
extern "C" void kernel_launch(void* const* d_in, const int* in_sizes, int n_in,
                              void* d_out, int out_size) {
    const float* h      = (const float*)d_in[0];   // [50000, 256]
    const float* norm   = (const float*)d_in[1];   // [50000, 1]
    const float* weight = (const float*)d_in[2];   // [256, 64]
    const float* bias   = (const float*)d_in[3];   // [64]
    const int*   src    = (const int*)d_in[4];     // [800000]
    const int*   dst    = (const int*)d_in[5];     // [800000]
    float* out = (float*)d_out;                    // [50000, 64]

    static cudaStream_t sA = nullptr, sB = nullptr;
    static cudaEvent_t  eFork = nullptr, eA = nullptr, eB = nullptr;
    if (!sA) {
        cudaStreamCreateWithFlags(&sA, cudaStreamNonBlocking);
        cudaStreamCreateWithFlags(&sB, cudaStreamNonBlocking);
        cudaEventCreateWithFlags(&eFork, cudaEventDisableTiming);
        cudaEventCreateWithFlags(&eA, cudaEventDisableTiming);
        cudaEventCreateWithFlags(&eB, cudaEventDisableTiming);
    }

    // tiny init on capture-origin stream
    init_kernel<<<(N_NODES + 255) / 256, 256>>>(weight);

    // Fork
    cudaEventRecord(eFork, 0);
    cudaStreamWaitEvent(sA, eFork, 0);
    cudaStreamWaitEvent(sB, eFork, 0);

    // Branch A: GEMM
    gemm_tf32_kernel<<<(N_NODES + 127) / 128, 256, 0, sA>>>(h, norm);

    // Branch B: bucket pre-fill (L2 warm) then placement
    prefill_kernel<<<(N_NODES * CAP / 8 + 255) / 256, 256, 0, sB>>>();
    place_kernel<<<(N_EDGES + 255) / 256, 256, 0, sB>>>(src, dst);

    cudaEventRecord(eA, sA);
    cudaEventRecord(eB, sB);

    // Join, then warp-per-node aggregate
    cudaStreamWaitEvent(0, eA, 0);
    cudaStreamWaitEvent(0, eB, 0);
    aggregate_kernel<<<(N_NODES * 32 + 255) / 256, 256>>>(norm, bias, out);
}

// round 16
// speedup vs baseline: 1.0992x; 1.0992x over previous
#include <cuda_runtime.h>
#include <cuda_fp16.h>
#include <cstdint>

#define N_NODES   50000
#define N_EDGES   800000
#define IN_FEATS  256
#define OUT_FEATS 64
#define CAP       64          // bucket capacity; P(Poisson(16) > 64) ~ 2e-18/node
#define DUMMY     50000       // dummy src id -> all-zero row of g_hw_h

// Scratch (__device__ globals: no allocation allowed)
__device__ __half    g_hw_h[(N_NODES + 1) * OUT_FEATS]; // +1 zero dummy row
__device__ uint32_t  g_w_tf32[IN_FEATS * OUT_FEATS];    // W pre-converted to tf32
__device__ int       g_cnt[N_NODES];                    // per-dst degree counters
__device__ uint16_t  g_esrc16[N_NODES * CAP];           // bucketed src ids (6.4MB)

// ---------------------------------------------------------------------------
// Kernel 0: fused init, GRID-STRIDE version (512 CTAs, ~3 uint4 stores/thread,
// MLP>=3 streaming writes instead of 1563 one-shot CTAs).
// W->tf32, counter zero, bucket pre-fill (L2 warm + DUMMY tail), dummy row.
// ---------------------------------------------------------------------------
__global__ __launch_bounds__(256)
void init_kernel(const float* __restrict__ W) {
    const int nthr = gridDim.x * blockDim.x;           // 131072
    int tid0 = blockIdx.x * blockDim.x + threadIdx.x;

    // bucket pre-fill: 400000 uint4s
    const uint4 f = make_uint4(0xC350C350u, 0xC350C350u, 0xC350C350u, 0xC350C350u);
    for (int i = tid0; i < N_NODES * CAP / 8; i += nthr)
        *reinterpret_cast<uint4*>(g_esrc16 + (size_t)i * 8) = f;

    // counter zero: 12500 int4s
    for (int i = tid0; i < N_NODES / 4; i += nthr)
        *reinterpret_cast<int4*>(g_cnt + i * 4) = make_int4(0, 0, 0, 0);
    if (tid0 < N_NODES % 4) g_cnt[(N_NODES / 4) * 4 + tid0] = 0;

    // dummy row zero: 8 uint4s
    if (tid0 < OUT_FEATS / 8)
        *reinterpret_cast<uint4*>(g_hw_h + (size_t)DUMMY * OUT_FEATS + tid0 * 8) =
            make_uint4(0u, 0u, 0u, 0u);

    // W -> tf32: 4096 float4s
    for (int i = tid0; i < IN_FEATS * OUT_FEATS / 4; i += nthr) {
        float4 v = *reinterpret_cast<const float4*>(W + i * 4);
        uint4 u;
        asm("cvt.rna.tf32.f32 %0, %1;" : "=r"(u.x) : "f"(v.x));
        asm("cvt.rna.tf32.f32 %0, %1;" : "=r"(u.y) : "f"(v.y));
        asm("cvt.rna.tf32.f32 %0, %1;" : "=r"(u.z) : "f"(v.z));
        asm("cvt.rna.tf32.f32 %0, %1;" : "=r"(u.w) : "f"(v.w));
        *reinterpret_cast<uint4*>(g_w_tf32 + (size_t)i * 4) = u;
    }
}

// ---------------------------------------------------------------------------
// Kernel 1: hw = (h @ W) * norm  -- tf32 mma.sync, 3-stage cp.async pipeline.
// Tile 128x64, BK=32 (8 chunks), 256 threads. smem ~83KB -> 2 CTAs/SM.
// (Exact R10 configuration -- best measured. 4-stage is geometrically
// impossible at 2 CTAs/SM: PAD_B must be >= 64+8 = 72.)
// ---------------------------------------------------------------------------
#define PAD_A 36   // bank stride 4 -> A-frag banks (4g+tg)%32 unique
#define PAD_B 72   // >= row width 64; 72 = 8 mod 32 -> B-frag banks unique
#define STAGES 3

__device__ __forceinline__ uint32_t f2tf32(float f) {
    uint32_t u;
    asm("cvt.rna.tf32.f32 %0, %1;" : "=r"(u) : "f"(f));
    return u;
}

__device__ __forceinline__ void cp_async16(void* smem_dst, const void* gmem_src) {
    uint32_t s;
    asm("{ .reg .u64 t; cvta.to.shared.u64 t, %1; cvt.u32.u64 %0, t; }"
        : "=r"(s) : "l"(smem_dst));
    asm volatile("cp.async.cg.shared.global [%0], [%1], 16;" :: "r"(s), "l"(gmem_src));
}

__global__ __launch_bounds__(256, 2)
void gemm_tf32_kernel(const float* __restrict__ h,
                      const float* __restrict__ norm) {
    __shared__ uint32_t shA[STAGES][128 * PAD_A];   // raw fp32 bits, 55.3KB
    __shared__ uint32_t shB[STAGES][32 * PAD_B];    // tf32 bits,     27.6KB

    const int tid  = threadIdx.x;
    const int warp = tid >> 5;
    const int lane = tid & 31;
    const int g    = lane >> 2;
    const int tg   = lane & 3;
    const int rowBase = blockIdx.x * 128;

    float acc[8][4];
    #pragma unroll
    for (int t = 0; t < 8; t++)
        #pragma unroll
        for (int i = 0; i < 4; i++) acc[t][i] = 0.f;

    auto stage = [&](int kk, int b) {
        #pragma unroll
        for (int j = 0; j < 4; j++) {
            int idx = tid + j * 256;       // 0..1023
            int r   = idx >> 3;            // 0..127
            int k4  = idx & 7;             // 0..7
            int row = rowBase + r;
            if (row >= N_NODES) row = N_NODES - 1;   // clamp: junk computed, never stored
            cp_async16(&shA[b][r * PAD_A + k4 * 4],
                       h + (size_t)row * IN_FEATS + kk + k4 * 4);
        }
        #pragma unroll
        for (int j = 0; j < 2; j++) {
            int idx = tid + j * 256;       // 0..511
            int r   = idx >> 4;            // 0..31
            int k4  = idx & 15;            // 0..15
            cp_async16(&shB[b][r * PAD_B + k4 * 4],
                       g_w_tf32 + (size_t)(kk + r) * OUT_FEATS + k4 * 4);
        }
        asm volatile("cp.async.commit_group;" ::: "memory");
    };

    stage(0, 0);
    stage(32, 1);

    #pragma unroll
    for (int c = 0; c < 8; c++) {          // 8 K-chunks of 32
        if (c < 7) asm volatile("cp.async.wait_group 1;" ::: "memory");
        else       asm volatile("cp.async.wait_group 0;" ::: "memory");
        __syncthreads();
        if (c + 2 < 8) stage((c + 2) * 32, (c + 2) % STAGES);

        const uint32_t* A = shA[c % STAGES];
        const uint32_t* B = shB[c % STAGES];
        const int ar = warp * 16;
        #pragma unroll
        for (int k8 = 0; k8 < 32; k8 += 8) {
            uint32_t a0 = f2tf32(__uint_as_float(A[(ar + g    ) * PAD_A + k8 + tg    ]));
            uint32_t a1 = f2tf32(__uint_as_float(A[(ar + g + 8) * PAD_A + k8 + tg    ]));
            uint32_t a2 = f2tf32(__uint_as_float(A[(ar + g    ) * PAD_A + k8 + tg + 4]));
            uint32_t a3 = f2tf32(__uint_as_float(A[(ar + g + 8) * PAD_A + k8 + tg + 4]));
            #pragma unroll
            for (int t = 0; t < 8; t++) {
                uint32_t b0 = B[(k8 + tg    ) * PAD_B + t * 8 + g];
                uint32_t b1 = B[(k8 + tg + 4) * PAD_B + t * 8 + g];
                asm volatile(
                    "mma.sync.aligned.m16n8k8.row.col.f32.tf32.tf32.f32 "
                    "{%0,%1,%2,%3}, {%4,%5,%6,%7}, {%8,%9}, {%0,%1,%2,%3};"
                    : "+f"(acc[t][0]), "+f"(acc[t][1]), "+f"(acc[t][2]), "+f"(acc[t][3])
                    : "r"(a0), "r"(a1), "r"(a2), "r"(a3), "r"(b0), "r"(b1));
            }
        }
        __syncthreads();
    }

    int r0 = rowBase + warp * 16 + g;
    int r1 = r0 + 8;
    if (r0 < N_NODES) {
        float nv = norm[r0];
        #pragma unroll
        for (int t = 0; t < 8; t++) {
            __half2 p = __floats2half2_rn(acc[t][0] * nv, acc[t][1] * nv);
            *reinterpret_cast<__half2*>(g_hw_h + (size_t)r0 * OUT_FEATS + t * 8 + tg * 2) = p;
        }
    }
    if (r1 < N_NODES) {
        float nv = norm[r1];
        #pragma unroll
        for (int t = 0; t < 8; t++) {
            __half2 p = __floats2half2_rn(acc[t][2] * nv, acc[t][3] * nv);
            *reinterpret_cast<__half2*>(g_hw_h + (size_t)r1 * OUT_FEATS + t * 8 + tg * 2) = p;
        }
    }
}

// ---------------------------------------------------------------------------
// Kernel 2: bucket placement, 1 edge per thread, uint16 src ids.
// ---------------------------------------------------------------------------
__global__ __launch_bounds__(256)
void place_kernel(const int* __restrict__ src, const int* __restrict__ dst) {
    int e = blockIdx.x * blockDim.x + threadIdx.x;
    if (e < N_EDGES) {
        int d = __ldg(dst + e);
        int s = __ldg(src + e);
        int p = atomicAdd(&g_cnt[d], 1);
        g_esrc16[d * CAP + (p & (CAP - 1))] = (uint16_t)s;  // masked: OOB-safe
    }
}

// ---------------------------------------------------------------------------
// Kernel 3: bucket aggregation + fused epilogue (exact R10 version).
// 8 threads per node; batch-8 ids -> 8 independent 16B gathers (MLP=8);
// tail slots hold pre-filled DUMMY -> hot zero row.
// ---------------------------------------------------------------------------
__global__ __launch_bounds__(256)
void aggregate_kernel(const float* __restrict__ norm,
                      const float* __restrict__ bias,
                      float* __restrict__ out) {
    int gid = blockIdx.x * blockDim.x + threadIdx.x;  // 400000 threads
    int v = gid >> 3;
    int c = gid & 7;
    if (v >= N_NODES) return;

    const uint16_t* el = g_esrc16 + (size_t)v * CAP;
    int deg = g_cnt[v];
    if (deg > CAP) deg = CAP;
    int padded = (deg + 7) & ~7;

    float acc[8];
    #pragma unroll
    for (int i = 0; i < 8; i++) acc[i] = 0.f;

    for (int base = 0; base < padded; base += 8) {
        uint4 ev = *reinterpret_cast<const uint4*>(el + base);  // 8 ids (tail = DUMMY)
        int id[8];
        id[0] = ev.x & 0xFFFF; id[1] = ev.x >> 16;
        id[2] = ev.y & 0xFFFF; id[3] = ev.y >> 16;
        id[4] = ev.z & 0xFFFF; id[5] = ev.z >> 16;
        id[6] = ev.w & 0xFFFF; id[7] = ev.w >> 16;

        uint4 raw[8];
        #pragma unroll
        for (int i = 0; i < 8; i++)
            raw[i] = *reinterpret_cast<const uint4*>(
                g_hw_h + (size_t)id[i] * OUT_FEATS + c * 8);

        #pragma unroll
        for (int i = 0; i < 8; i++) {
            const __half2* hp = reinterpret_cast<const __half2*>(&raw[i]);
            #pragma unroll
            for (int q = 0; q < 4; q++) {
                float2 f = __half22float2(hp[q]);
                acc[q * 2]     += f.x;
                acc[q * 2 + 1] += f.y;
            }
        }
    }

    float nv = norm[v];
    const float4* bp = reinterpret_cast<const float4*>(bias + c * 8);
    float4 b0 = bp[0], b1 = bp[1];
    float4 o0, o1;
    o0.x = fmaxf(fmaf(acc[0], nv, b0.x), 0.f);
    o0.y = fmaxf(fmaf(acc[1], nv, b0.y), 0.f);
    o0.z = fmaxf(fmaf(acc[2], nv, b0.z), 0.f);
    o0.w = fmaxf(fmaf(acc[3], nv, b0.w), 0.f);
    o1.x = fmaxf(fmaf(acc[4], nv, b1.x), 0.f);
    o1.y = fmaxf(fmaf(acc[5], nv, b1.y), 0.f);
    o1.z = fmaxf(fmaf(acc[6], nv, b1.z), 0.f);
    o1.w = fmaxf(fmaf(acc[7], nv, b1.w), 0.f);
    float4* op = reinterpret_cast<float4*>(out + (size_t)v * OUT_FEATS + c * 8);
    op[0] = o0;
    op[1] = o1;
}

// ---------------------------------------------------------------------------
// Launch: R10 fork/join (measured best).
// ---------------------------------------------------------------------------
extern "C" void kernel_launch(void* const* d_in, const int* in_sizes, int n_in,
                              void* d_out, int out_size) {
    const float* h      = (const float*)d_in[0];   // [50000, 256]
    const float* norm   = (const float*)d_in[1];   // [50000, 1]
    const float* weight = (const float*)d_in[2];   // [256, 64]
    const float* bias   = (const float*)d_in[3];   // [64]
    const int*   src    = (const int*)d_in[4];     // [800000]
    const int*   dst    = (const int*)d_in[5];     // [800000]
    float* out = (float*)d_out;                    // [50000, 64]

    static cudaStream_t sA = nullptr, sB = nullptr;
    static cudaEvent_t  eFork = nullptr, eA = nullptr, eB = nullptr;
    if (!sA) {
        cudaStreamCreateWithFlags(&sA, cudaStreamNonBlocking);
        cudaStreamCreateWithFlags(&sB, cudaStreamNonBlocking);
        cudaEventCreateWithFlags(&eFork, cudaEventDisableTiming);
        cudaEventCreateWithFlags(&eA, cudaEventDisableTiming);
        cudaEventCreateWithFlags(&eB, cudaEventDisableTiming);
    }

    // grid-stride init on capture-origin stream (512 CTAs, streaming stores)
    init_kernel<<<512, 256>>>(weight);

    // Fork to two side streams
    cudaEventRecord(eFork, 0);
    cudaStreamWaitEvent(sA, eFork, 0);
    cudaStreamWaitEvent(sB, eFork, 0);

    gemm_tf32_kernel<<<(N_NODES + 127) / 128, 256, 0, sA>>>(h, norm);
    place_kernel<<<(N_EDGES + 255) / 256, 256, 0, sB>>>(src, dst);

    cudaEventRecord(eA, sA);
    cudaEventRecord(eB, sB);

    // Join on capture-origin stream, then aggregate
    cudaStreamWaitEvent(0, eA, 0);
    cudaStreamWaitEvent(0, eB, 0);
    aggregate_kernel<<<(N_NODES * 8 + 255) / 256, 256>>>(norm, bias, out);
}

// round 17
// speedup vs baseline: 1.1404x; 1.0375x over previous
#include <cuda_runtime.h>
#include <cuda_fp16.h>
#include <cstdint>

#define N_NODES   50000
#define N_EDGES   800000
#define IN_FEATS  256
#define OUT_FEATS 64
#define CAP       64          // bucket capacity; P(Poisson(16) > 64) ~ 2e-18/node
#define DUMMY     50000       // dummy src id -> all-zero row of g_hw_h

// Scratch (__device__ globals: no allocation allowed)
__device__ __half    g_hw_h[(N_NODES + 1) * OUT_FEATS]; // +1 zero dummy row
__device__ uint32_t  g_w_tf32[IN_FEATS * OUT_FEATS];    // W pre-converted to tf32
__device__ int       g_cnt[N_NODES];                    // per-dst degree counters
__device__ uint16_t  g_esrc16[N_NODES * CAP];           // bucketed src ids (6.4MB)

// ---------------------------------------------------------------------------
// Kernel 0: fused init (exact R10): W->tf32, counter zero, bucket pre-fill
// (warms L2 for place's scattered stores + DUMMY tail padding), dummy row.
// ---------------------------------------------------------------------------
__global__ __launch_bounds__(256)
void init_kernel(const float* __restrict__ W) {
    int gid = blockIdx.x * blockDim.x + threadIdx.x;
    if (gid < N_NODES * CAP / 8) {
        uint4 f = make_uint4(0xC350C350u, 0xC350C350u, 0xC350C350u, 0xC350C350u); // 50000
        *reinterpret_cast<uint4*>(g_esrc16 + gid * 8) = f;
    }
    if (gid < N_NODES) g_cnt[gid] = 0;
    if (gid < OUT_FEATS / 8)
        *reinterpret_cast<uint4*>(g_hw_h + (size_t)DUMMY * OUT_FEATS + gid * 8) =
            make_uint4(0u, 0u, 0u, 0u);
    if (gid < IN_FEATS * OUT_FEATS / 4) {
        float4 v = *reinterpret_cast<const float4*>(W + gid * 4);
        uint4 u;
        asm("cvt.rna.tf32.f32 %0, %1;" : "=r"(u.x) : "f"(v.x));
        asm("cvt.rna.tf32.f32 %0, %1;" : "=r"(u.y) : "f"(v.y));
        asm("cvt.rna.tf32.f32 %0, %1;" : "=r"(u.z) : "f"(v.z));
        asm("cvt.rna.tf32.f32 %0, %1;" : "=r"(u.w) : "f"(v.w));
        *reinterpret_cast<uint4*>(g_w_tf32 + gid * 4) = u;
    }
}

// ---------------------------------------------------------------------------
// Kernel 1: hw = (h @ W) * norm  -- tf32 mma.sync, 3-stage cp.async pipeline.
// Tile 128x64, BK=32 (8 chunks), 256 threads. smem ~83KB -> 2 CTAs/SM.
// (Exact R10 configuration -- best measured.)
// ---------------------------------------------------------------------------
#define PAD_A 36   // bank stride 4 -> A-frag banks (4g+tg)%32 unique
#define PAD_B 72   // >= row width 64; 72 = 8 mod 32 -> B-frag banks unique
#define STAGES 3

__device__ __forceinline__ uint32_t f2tf32(float f) {
    uint32_t u;
    asm("cvt.rna.tf32.f32 %0, %1;" : "=r"(u) : "f"(f));
    return u;
}

__device__ __forceinline__ void cp_async16(void* smem_dst, const void* gmem_src) {
    uint32_t s;
    asm("{ .reg .u64 t; cvta.to.shared.u64 t, %1; cvt.u32.u64 %0, t; }"
        : "=r"(s) : "l"(smem_dst));
    asm volatile("cp.async.cg.shared.global [%0], [%1], 16;" :: "r"(s), "l"(gmem_src));
}

__global__ __launch_bounds__(256, 2)
void gemm_tf32_kernel(const float* __restrict__ h,
                      const float* __restrict__ norm) {
    __shared__ uint32_t shA[STAGES][128 * PAD_A];   // raw fp32 bits, 55.3KB
    __shared__ uint32_t shB[STAGES][32 * PAD_B];    // tf32 bits,     27.6KB

    const int tid  = threadIdx.x;
    const int warp = tid >> 5;
    const int lane = tid & 31;
    const int g    = lane >> 2;
    const int tg   = lane & 3;
    const int rowBase = blockIdx.x * 128;

    float acc[8][4];
    #pragma unroll
    for (int t = 0; t < 8; t++)
        #pragma unroll
        for (int i = 0; i < 4; i++) acc[t][i] = 0.f;

    auto stage = [&](int kk, int b) {
        #pragma unroll
        for (int j = 0; j < 4; j++) {
            int idx = tid + j * 256;       // 0..1023
            int r   = idx >> 3;            // 0..127
            int k4  = idx & 7;             // 0..7
            int row = rowBase + r;
            if (row >= N_NODES) row = N_NODES - 1;   // clamp: junk computed, never stored
            cp_async16(&shA[b][r * PAD_A + k4 * 4],
                       h + (size_t)row * IN_FEATS + kk + k4 * 4);
        }
        #pragma unroll
        for (int j = 0; j < 2; j++) {
            int idx = tid + j * 256;       // 0..511
            int r   = idx >> 4;            // 0..31
            int k4  = idx & 15;            // 0..15
            cp_async16(&shB[b][r * PAD_B + k4 * 4],
                       g_w_tf32 + (size_t)(kk + r) * OUT_FEATS + k4 * 4);
        }
        asm volatile("cp.async.commit_group;" ::: "memory");
    };

    stage(0, 0);
    stage(32, 1);

    #pragma unroll
    for (int c = 0; c < 8; c++) {          // 8 K-chunks of 32
        if (c < 7) asm volatile("cp.async.wait_group 1;" ::: "memory");
        else       asm volatile("cp.async.wait_group 0;" ::: "memory");
        __syncthreads();
        if (c + 2 < 8) stage((c + 2) * 32, (c + 2) % STAGES);

        const uint32_t* A = shA[c % STAGES];
        const uint32_t* B = shB[c % STAGES];
        const int ar = warp * 16;
        #pragma unroll
        for (int k8 = 0; k8 < 32; k8 += 8) {
            uint32_t a0 = f2tf32(__uint_as_float(A[(ar + g    ) * PAD_A + k8 + tg    ]));
            uint32_t a1 = f2tf32(__uint_as_float(A[(ar + g + 8) * PAD_A + k8 + tg    ]));
            uint32_t a2 = f2tf32(__uint_as_float(A[(ar + g    ) * PAD_A + k8 + tg + 4]));
            uint32_t a3 = f2tf32(__uint_as_float(A[(ar + g + 8) * PAD_A + k8 + tg + 4]));
            #pragma unroll
            for (int t = 0; t < 8; t++) {
                uint32_t b0 = B[(k8 + tg    ) * PAD_B + t * 8 + g];
                uint32_t b1 = B[(k8 + tg + 4) * PAD_B + t * 8 + g];
                asm volatile(
                    "mma.sync.aligned.m16n8k8.row.col.f32.tf32.tf32.f32 "
                    "{%0,%1,%2,%3}, {%4,%5,%6,%7}, {%8,%9}, {%0,%1,%2,%3};"
                    : "+f"(acc[t][0]), "+f"(acc[t][1]), "+f"(acc[t][2]), "+f"(acc[t][3])
                    : "r"(a0), "r"(a1), "r"(a2), "r"(a3), "r"(b0), "r"(b1));
            }
        }
        __syncthreads();
    }

    int r0 = rowBase + warp * 16 + g;
    int r1 = r0 + 8;
    if (r0 < N_NODES) {
        float nv = norm[r0];
        #pragma unroll
        for (int t = 0; t < 8; t++) {
            __half2 p = __floats2half2_rn(acc[t][0] * nv, acc[t][1] * nv);
            *reinterpret_cast<__half2*>(g_hw_h + (size_t)r0 * OUT_FEATS + t * 8 + tg * 2) = p;
        }
    }
    if (r1 < N_NODES) {
        float nv = norm[r1];
        #pragma unroll
        for (int t = 0; t < 8; t++) {
            __half2 p = __floats2half2_rn(acc[t][2] * nv, acc[t][3] * nv);
            *reinterpret_cast<__half2*>(g_hw_h + (size_t)r1 * OUT_FEATS + t * 8 + tg * 2) = p;
        }
    }
}

// ---------------------------------------------------------------------------
// Kernel 2: bucket placement, 1 edge per thread, uint16 src ids.
// ---------------------------------------------------------------------------
__global__ __launch_bounds__(256)
void place_kernel(const int* __restrict__ src, const int* __restrict__ dst) {
    int e = blockIdx.x * blockDim.x + threadIdx.x;
    if (e < N_EDGES) {
        int d = __ldg(dst + e);
        int s = __ldg(src + e);
        int p = atomicAdd(&g_cnt[d], 1);
        g_esrc16[d * CAP + (p & (CAP - 1))] = (uint16_t)s;  // masked: OOB-safe
    }
}

// ---------------------------------------------------------------------------
// Kernel 3: PERSISTENT bucket aggregation + fused epilogue.
// Grid = one full wave (1184 CTAs); threads grid-stride over the 400000
// (node, col-group) work items. Removes the 1.3-wave quantization and
// spreads degree variance across the stride instead of late CTAs.
// Body identical to R10's batch-8 (best measured).
// ---------------------------------------------------------------------------
#define AGG_CTAS 1184   // 148 SMs x 8 CTAs of 256 thr = exactly one wave

__global__ __launch_bounds__(256)
void aggregate_kernel(const float* __restrict__ norm,
                      const float* __restrict__ bias,
                      float* __restrict__ out) {
    const int nthr = AGG_CTAS * 256;
    for (int gid = blockIdx.x * blockDim.x + threadIdx.x;
         gid < N_NODES * 8; gid += nthr) {
        int v = gid >> 3;
        int c = gid & 7;

        const uint16_t* el = g_esrc16 + (size_t)v * CAP;
        int deg = g_cnt[v];
        if (deg > CAP) deg = CAP;
        int padded = (deg + 7) & ~7;

        float acc[8];
        #pragma unroll
        for (int i = 0; i < 8; i++) acc[i] = 0.f;

        for (int base = 0; base < padded; base += 8) {
            uint4 ev = *reinterpret_cast<const uint4*>(el + base);  // 8 ids (tail = DUMMY)
            int id[8];
            id[0] = ev.x & 0xFFFF; id[1] = ev.x >> 16;
            id[2] = ev.y & 0xFFFF; id[3] = ev.y >> 16;
            id[4] = ev.z & 0xFFFF; id[5] = ev.z >> 16;
            id[6] = ev.w & 0xFFFF; id[7] = ev.w >> 16;

            uint4 raw[8];
            #pragma unroll
            for (int i = 0; i < 8; i++)
                raw[i] = *reinterpret_cast<const uint4*>(
                    g_hw_h + (size_t)id[i] * OUT_FEATS + c * 8);

            #pragma unroll
            for (int i = 0; i < 8; i++) {
                const __half2* hp = reinterpret_cast<const __half2*>(&raw[i]);
                #pragma unroll
                for (int q = 0; q < 4; q++) {
                    float2 f = __half22float2(hp[q]);
                    acc[q * 2]     += f.x;
                    acc[q * 2 + 1] += f.y;
                }
            }
        }

        float nv = norm[v];
        const float4* bp = reinterpret_cast<const float4*>(bias + c * 8);
        float4 b0 = bp[0], b1 = bp[1];
        float4 o0, o1;
        o0.x = fmaxf(fmaf(acc[0], nv, b0.x), 0.f);
        o0.y = fmaxf(fmaf(acc[1], nv, b0.y), 0.f);
        o0.z = fmaxf(fmaf(acc[2], nv, b0.z), 0.f);
        o0.w = fmaxf(fmaf(acc[3], nv, b0.w), 0.f);
        o1.x = fmaxf(fmaf(acc[4], nv, b1.x), 0.f);
        o1.y = fmaxf(fmaf(acc[5], nv, b1.y), 0.f);
        o1.z = fmaxf(fmaf(acc[6], nv, b1.z), 0.f);
        o1.w = fmaxf(fmaf(acc[7], nv, b1.w), 0.f);
        float4* op = reinterpret_cast<float4*>(out + (size_t)v * OUT_FEATS + c * 8);
        op[0] = o0;
        op[1] = o1;
    }
}

// ---------------------------------------------------------------------------
// Launch: R10 fork/join (measured best).
// ---------------------------------------------------------------------------
extern "C" void kernel_launch(void* const* d_in, const int* in_sizes, int n_in,
                              void* d_out, int out_size) {
    const float* h      = (const float*)d_in[0];   // [50000, 256]
    const float* norm   = (const float*)d_in[1];   // [50000, 1]
    const float* weight = (const float*)d_in[2];   // [256, 64]
    const float* bias   = (const float*)d_in[3];   // [64]
    const int*   src    = (const int*)d_in[4];     // [800000]
    const int*   dst    = (const int*)d_in[5];     // [800000]
    float* out = (float*)d_out;                    // [50000, 64]

    static cudaStream_t sA = nullptr, sB = nullptr;
    static cudaEvent_t  eFork = nullptr, eA = nullptr, eB = nullptr;
    if (!sA) {
        cudaStreamCreateWithFlags(&sA, cudaStreamNonBlocking);
        cudaStreamCreateWithFlags(&sB, cudaStreamNonBlocking);
        cudaEventCreateWithFlags(&eFork, cudaEventDisableTiming);
        cudaEventCreateWithFlags(&eA, cudaEventDisableTiming);
        cudaEventCreateWithFlags(&eB, cudaEventDisableTiming);
    }

    // init (W conv + counter zero + bucket pre-fill) on capture-origin stream
    init_kernel<<<(N_NODES * CAP / 8 + 255) / 256, 256>>>(weight);

    // Fork to two side streams
    cudaEventRecord(eFork, 0);
    cudaStreamWaitEvent(sA, eFork, 0);
    cudaStreamWaitEvent(sB, eFork, 0);

    gemm_tf32_kernel<<<(N_NODES + 127) / 128, 256, 0, sA>>>(h, norm);
    place_kernel<<<(N_EDGES + 255) / 256, 256, 0, sB>>>(src, dst);

    cudaEventRecord(eA, sA);
    cudaEventRecord(eB, sB);

    // Join on capture-origin stream, then persistent aggregate
    cudaStreamWaitEvent(0, eA, 0);
    cudaStreamWaitEvent(0, eB, 0);
    aggregate_kernel<<<AGG_CTAS, 256>>>(norm, bias, out);
}